// round 1
// baseline (speedup 1.0000x reference)
#include <cuda_runtime.h>
#include <cuda_bf16.h>
#include <cstdint>

// Problem constants
#define T_ 8
#define L_ 8
#define N_ 500
#define D_ 64
#define K_ 12
#define S_ 2
#define R_ (T_*L_*N_)        // 32000 rows of (t,l,n)
#define ELEMS (R_*D_)        // 2048000

// ---------------- scratch buffers (no allocation allowed) ----------------
__device__ float g_dyn[ELEMS];       // all_dyn (T,L,N,D)
__device__ float g_x[ELEMS];         // current x during attention stack
__device__ float g_q[ELEMS];         // q = x @ wq
__device__ float g_k[ELEMS];         // k = x @ wk (pre-gather)
__device__ float g_mixb[2][ELEMS];   // mixed dyn / sta
__device__ float g_h[T_*N_];         // LSTM h_last

__device__ __forceinline__ float sigf(float x) {
    return 1.f / (1.f + __expf(-x));
}

// ---------------- 1. evolution scan ----------------
// block: 256 threads = 4 rows x 64 lanes; grid: 1000 (L*N/4 rows)
__global__ void evo_kernel(const float* __restrict__ stat,
                           const float* __restrict__ thre,
                           const float* __restrict__ dynn,
                           const float* __restrict__ w1,
                           float* __restrict__ out_nowfinal,
                           float* __restrict__ out_diffs) {
    __shared__ float w1_s[128 * 64];
    __shared__ float now_s[4][64];
    __shared__ float st_s[4][64];
    int tid = threadIdx.x;
    for (int i = tid; i < 8192; i += 256) w1_s[i] = w1[i];
    int r = tid >> 6, e = tid & 63;
    int row = blockIdx.x * 4 + r;             // (l*N + n), < 4000
    float nowv = dynn[(size_t)row * 64 + e];
    now_s[r][e] = nowv;
    g_dyn[(size_t)row * 64 + e] = nowv;       // all_dyn[t=0]
    __syncthreads();
    for (int t = 1; t < T_; t++) {
        size_t idx = (size_t)t * (L_ * N_) + row;
        float th = thre[idx];
        st_s[r][e] = stat[idx * 64 + e];
        __syncthreads();
        float sum = 0.f;
#pragma unroll 16
        for (int d = 0; d < 64; d++) {
            sum = fmaf(now_s[r][d], w1_s[d * 64 + e], sum);
            sum = fmaf(st_s[r][d], w1_s[(64 + d) * 64 + e], sum);
        }
        float nv = now_s[r][e];
        float val = sigf(sum * th + nv * (1.f - th));
        g_dyn[idx * 64 + e] = val;
        out_diffs[((size_t)(t - 1) * (L_ * N_) + row) * 64 + e] = val - nv;
        if (t == T_ - 1) out_nowfinal[(size_t)row * 64 + e] = val;
        __syncthreads();
        now_s[r][e] = val;
        __syncthreads();
    }
}

// ---------------- 2. pass1: q = x@wq, k = x@wk ----------------
// block: 256 threads, 64 rows per block; grid 500
__global__ void pass1_kernel(const float* __restrict__ x,
                             const float* __restrict__ wq,
                             const float* __restrict__ wk) {
    __shared__ float wq_s[64 * 64];
    __shared__ float wk_s[64 * 64];
    __shared__ float A_s[64 * 64];
    int tid = threadIdx.x;
    for (int i = tid; i < 4096; i += 256) {
        wq_s[i] = wq[i];
        wk_s[i] = wk[i];
    }
    {
        const float4* xv = (const float4*)(x + (size_t)blockIdx.x * 64 * 64);
        float4* av = (float4*)A_s;
        for (int i = tid; i < 1024; i += 256) av[i] = xv[i];
    }
    __syncthreads();
    int w = tid >> 5, lane = tid & 31;
    float acc[8][4];
#pragma unroll
    for (int r = 0; r < 8; r++)
#pragma unroll
        for (int c = 0; c < 4; c++) acc[r][c] = 0.f;

#pragma unroll
    for (int dc = 0; dc < 64; dc += 8) {
        float wqr0[8], wqr1[8], wkr0[8], wkr1[8];
#pragma unroll
        for (int j = 0; j < 8; j++) {
            wqr0[j] = wq_s[(dc + j) * 64 + lane];
            wqr1[j] = wq_s[(dc + j) * 64 + lane + 32];
            wkr0[j] = wk_s[(dc + j) * 64 + lane];
            wkr1[j] = wk_s[(dc + j) * 64 + lane + 32];
        }
#pragma unroll
        for (int r = 0; r < 8; r++) {
            int rowl = w * 8 + r;
#pragma unroll
            for (int j = 0; j < 8; j++) {
                float a = A_s[rowl * 64 + dc + j];
                acc[r][0] = fmaf(a, wqr0[j], acc[r][0]);
                acc[r][1] = fmaf(a, wqr1[j], acc[r][1]);
                acc[r][2] = fmaf(a, wkr0[j], acc[r][2]);
                acc[r][3] = fmaf(a, wkr1[j], acc[r][3]);
            }
        }
    }
    size_t base = (size_t)blockIdx.x * 64 * 64;
#pragma unroll
    for (int r = 0; r < 8; r++) {
        size_t ro = base + (size_t)(w * 8 + r) * 64;
        g_q[ro + lane] = acc[r][0];
        g_q[ro + lane + 32] = acc[r][1];
        g_k[ro + lane] = acc[r][2];
        g_k[ro + lane + 32] = acc[r][3];
    }
}

// ---------------- 3. pass2: gather + softmax attention + wd + sigmoid ----------------
// block 256 (8 warps), 32 rows per block (4 per warp, 2 pairs); grid 1000
__global__ void pass2_kernel(const int* __restrict__ neigh,
                             const float* __restrict__ wd) {
    __shared__ float wd_s[64 * 64];
    __shared__ float outbuf[8][2][64];
    int tid = threadIdx.x;
    for (int i = tid; i < 4096; i += 256) wd_s[i] = wd[i];
    __syncthreads();
    int w = tid >> 5, lane = tid & 31;

    for (int pair = 0; pair < 2; pair++) {
        int row0 = blockIdx.x * 32 + w * 4 + pair * 2;
#pragma unroll
        for (int rr = 0; rr < 2; rr++) {
            int row = row0 + rr;
            int n = row % N_;
            int tl = row / N_;
            const float* qrow = g_q + (size_t)row * 64;
            float q0 = qrow[lane], q1 = qrow[lane + 32];
            float k0[K_], k1[K_], dots[K_];
#pragma unroll
            for (int j = 0; j < K_; j++) {
                int nb = neigh[n * K_ + j];
                const float* krow = g_k + ((size_t)tl * N_ + nb) * 64;
                k0[j] = krow[lane];
                k1[j] = krow[lane + 32];
                float d = q0 * k0[j] + q1 * k1[j];
#pragma unroll
                for (int off = 16; off; off >>= 1)
                    d += __shfl_xor_sync(0xffffffffu, d, off);
                dots[j] = d;
            }
            float m = dots[0];
#pragma unroll
            for (int j = 1; j < K_; j++) m = fmaxf(m, dots[j]);
            float ssum = 0.f;
#pragma unroll
            for (int j = 0; j < K_; j++) {
                dots[j] = __expf(dots[j] - m);
                ssum += dots[j];
            }
            float inv = 1.f / ssum;
            float o0 = q0, o1 = q1;
#pragma unroll
            for (int j = 0; j < K_; j++) {
                float a = dots[j] * inv;
                o0 = fmaf(a, k0[j], o0);
                o1 = fmaf(a, k1[j], o1);
            }
            outbuf[w][rr][lane] = o0;
            outbuf[w][rr][lane + 32] = o1;
        }
        __syncwarp();
        float r00 = 0.f, r01 = 0.f, r10 = 0.f, r11 = 0.f;
#pragma unroll
        for (int d = 0; d < 64; d++) {
            float wd0 = wd_s[d * 64 + lane];
            float wd1 = wd_s[d * 64 + lane + 32];
            float a0 = outbuf[w][0][d];
            float a1 = outbuf[w][1][d];
            r00 = fmaf(a0, wd0, r00);
            r01 = fmaf(a0, wd1, r01);
            r10 = fmaf(a1, wd0, r10);
            r11 = fmaf(a1, wd1, r11);
        }
        float* xr0 = g_x + (size_t)row0 * 64;
        xr0[lane] = sigf(r00);
        xr0[lane + 32] = sigf(r01);
        float* xr1 = g_x + (size_t)(row0 + 1) * 64;
        xr1[lane] = sigf(r10);
        xr1[lane + 32] = sigf(r11);
        __syncwarp();
    }
}

// ---------------- 4. mix accumulate (+ sigmoid on last group) ----------------
// grid 8000 x 256 covers ELEMS exactly
__global__ void mix_kernel(const float* __restrict__ wmixb, int g, int branch) {
    size_t i = (size_t)blockIdx.x * 256 + threadIdx.x;
    float v = g_x[i] * wmixb[g * 64 + (threadIdx.x & 63)];
    float acc = v;
    if (g > 0) acc += g_mixb[branch][i];
    if (g == 2) acc = sigf(acc);
    g_mixb[branch][i] = acc;
}

// ---------------- 5. LSTM over L, warp per (t,n) ----------------
// grid 500 x 256 = 4000 warps
__global__ void lstm_kernel(const float* __restrict__ convw,
                            const float* __restrict__ convb) {
    __shared__ float cw[4 * 129];
    __shared__ float cb[4];
    int tid = threadIdx.x;
    for (int i = tid; i < 516; i += 256) cw[i] = convw[i];
    if (tid < 4) cb[tid] = convb[tid];
    __syncthreads();
    int gw = blockIdx.x * 8 + (tid >> 5);
    int lane = tid & 31;
    int t = gw / N_, n = gw % N_;
    int half = lane >> 4;           // 0: dyn, 1: sta
    int dl = (lane & 15) * 4;
    int dbase = half * 64 + dl;
    float wreg[4][4], wh[4], bb[4];
#pragma unroll
    for (int i = 0; i < 4; i++) {
#pragma unroll
        for (int q = 0; q < 4; q++) wreg[i][q] = cw[i * 129 + dbase + q];
        wh[i] = cw[i * 129 + 128];
        bb[i] = cb[i];
    }
    float h = 0.f, c = 0.f;
    for (int l = 0; l < L_; l++) {
        size_t off = (((size_t)t * L_ + l) * N_ + n) * 64 + dl;
        const float* src = half ? &g_mixb[1][off] : &g_mixb[0][off];
        float4 xin = *(const float4*)src;
        float s[4];
#pragma unroll
        for (int i = 0; i < 4; i++) {
            s[i] = xin.x * wreg[i][0] + xin.y * wreg[i][1] +
                   xin.z * wreg[i][2] + xin.w * wreg[i][3];
#pragma unroll
            for (int o = 16; o; o >>= 1)
                s[i] += __shfl_xor_sync(0xffffffffu, s[i], o);
        }
        float gi = sigf(s[0] + h * wh[0] + bb[0]);
        float gf = sigf(s[1] + h * wh[1] + bb[1]);
        float go = sigf(s[2] + h * wh[2] + bb[2]);
        float gg = tanhf(s[3] + h * wh[3] + bb[3]);
        c = gf * c + gi * gg;
        h = go * tanhf(c);
    }
    if (lane == 0) g_h[t * N_ + n] = h;
}

// ---------------- 6. final projection ----------------
// grid T_, block 512
__global__ void final_kernel(const float* __restrict__ finw,
                             const float* __restrict__ finb,
                             float* __restrict__ out) {
    __shared__ float hs[500];
    int t = blockIdx.x, tid = threadIdx.x;
    if (tid < 500) hs[tid] = g_h[t * N_ + tid];
    __syncthreads();
    if (tid < 500) {
        float acc = finb[tid];
        const float4* wr = (const float4*)(finw + (size_t)tid * 500);
#pragma unroll 5
        for (int m4 = 0; m4 < 125; m4++) {
            float4 wv = wr[m4];
            acc = fmaf(hs[m4 * 4 + 0], wv.x, acc);
            acc = fmaf(hs[m4 * 4 + 1], wv.y, acc);
            acc = fmaf(hs[m4 * 4 + 2], wv.z, acc);
            acc = fmaf(hs[m4 * 4 + 3], wv.w, acc);
        }
        out[t * N_ + tid] = sigf(acc);
    }
}

// ---------------- launcher ----------------
extern "C" void kernel_launch(void* const* d_in, const int* in_sizes, int n_in,
                              void* d_out, int out_size) {
    const float* stat = (const float*)d_in[0];   // all_data_static (T,L,N,D)
    const float* thre = (const float*)d_in[1];   // thre_nc (T,L,N,1)
    const float* dynn = (const float*)d_in[2];   // all_data_dynamic_now (L,N,D)
    const int* npoi = (const int*)d_in[3];
    const int* nroad = (const int*)d_in[4];
    const int* nrec = (const int*)d_in[5];
    const float* w1 = (const float*)d_in[6];     // (128,64)
    const float* wq = (const float*)d_in[7];     // (2,3,S,D,D)
    const float* wk = (const float*)d_in[8];
    const float* wdm = (const float*)d_in[9];
    const float* wmix = (const float*)d_in[10];  // (2,3,D)
    const float* convw = (const float*)d_in[11]; // (4,129)
    const float* convb = (const float*)d_in[12]; // (4,)
    const float* finw = (const float*)d_in[13];  // (N,N)
    const float* finb = (const float*)d_in[14];  // (N,)

    float* out = (float*)d_out;
    float* out_scores = out;                       // (T,N)       4000
    float* out_nowfinal = out + T_ * N_;           // (L,N,D)     256000
    float* out_diffs = out + T_ * N_ + L_ * N_ * D_; // (T-1,L,N,D) 1792000

    evo_kernel<<<1000, 256>>>(stat, thre, dynn, w1, out_nowfinal, out_diffs);

    float* p_dyn = nullptr;
    float* p_x = nullptr;
    cudaGetSymbolAddress((void**)&p_dyn, g_dyn);
    cudaGetSymbolAddress((void**)&p_x, g_x);

    const int* neighs[3] = {npoi, nroad, nrec};
    for (int b = 0; b < 2; b++) {
        const float* base = (b == 0) ? (const float*)p_dyn : stat;
        for (int g = 0; g < 3; g++) {
            const float* src = base;
            for (int s = 0; s < S_; s++) {
                size_t woff = (size_t)(((b * 3 + g) * S_) + s) * 64 * 64;
                pass1_kernel<<<500, 256>>>(src, wq + woff, wk + woff);
                pass2_kernel<<<1000, 256>>>(neighs[g], wdm + woff);
                src = (const float*)p_x;
            }
            mix_kernel<<<8000, 256>>>(wmix + b * 192, g, b);
        }
    }

    lstm_kernel<<<500, 256>>>(convw, convb);
    final_kernel<<<T_, 512>>>(finw, finb, out_scores);
}

// round 2
// speedup vs baseline: 1.2365x; 1.2365x over previous
#include <cuda_runtime.h>
#include <cuda_bf16.h>
#include <cstdint>

// Problem constants
#define T_ 8
#define L_ 8
#define N_ 500
#define D_ 64
#define K_ 12
#define S_ 2
#define RLN (L_*N_)          // 4000
#define R_ (T_*L_*N_)        // 32000 rows of (t,l,n)
#define ELEMS (R_*D_)        // 2048000

// ---------------- scratch buffers (no allocation allowed) ----------------
__device__ float g_dyn[ELEMS];          // all_dyn (T,L,N,D)
__device__ float g_q6[6][ELEMS];        // q per (branch,graph)
__device__ float g_k6[6][ELEMS];        // k per (branch,graph)
__device__ float g_x6[6][ELEMS];        // attention output per (branch,graph)
__device__ float g_mixb[2][ELEMS];      // mixed dyn / sta
__device__ float g_h[T_*N_];            // LSTM h_last

__device__ __forceinline__ float sigf(float x) {
    return 1.f / (1.f + __expf(-x));
}

// =====================================================================
// 1. evolution scan: grid 250, block 256 (64 lanes x 4 groups x 4 rows)
// =====================================================================
__global__ void evo_kernel(const float* __restrict__ stat,
                           const float* __restrict__ thre,
                           const float* __restrict__ dynn,
                           const float* __restrict__ w1,
                           float* __restrict__ out_nowfinal,
                           float* __restrict__ out_diffs) {
    __shared__ float w1T[64 * 132];       // w1T[e][d], d 0..127
    __shared__ float now_s[16][64];
    __shared__ float st_s[16][64];
    __shared__ float th_s[16];
    int tid = threadIdx.x;
    // transpose w1 (128x64) -> w1T[e][d]
    for (int i = tid; i < 8192; i += 256) {
        int d = i >> 6, e = i & 63;
        w1T[e * 132 + d] = w1[i];
    }
    int e = tid & 63, grp = tid >> 6;
    int row0 = blockIdx.x * 16;
#pragma unroll
    for (int i = 0; i < 4; i++) {
        int r = grp * 4 + i;
        float v = dynn[(size_t)(row0 + r) * 64 + e];
        now_s[r][e] = v;
        g_dyn[(size_t)(row0 + r) * 64 + e] = v;   // all_dyn[t=0]
    }
    __syncthreads();

    for (int t = 1; t < T_; t++) {
        size_t base = (size_t)t * RLN + row0;
        ((float4*)st_s)[tid] = ((const float4*)(stat + base * 64))[tid];
        if (tid < 16) th_s[tid] = thre[base + tid];
        __syncthreads();

        float sum[4] = {0.f, 0.f, 0.f, 0.f};
#pragma unroll
        for (int d = 0; d < 64; d += 4) {
            float4 wn = *(float4*)&w1T[e * 132 + d];
            float4 ws = *(float4*)&w1T[e * 132 + 64 + d];
#pragma unroll
            for (int i = 0; i < 4; i++) {
                float4 nv = *(float4*)&now_s[grp * 4 + i][d];
                float4 sv = *(float4*)&st_s[grp * 4 + i][d];
                sum[i] += nv.x * wn.x + nv.y * wn.y + nv.z * wn.z + nv.w * wn.w
                        + sv.x * ws.x + sv.y * ws.y + sv.z * ws.z + sv.w * ws.w;
            }
        }
        float vals[4];
#pragma unroll
        for (int i = 0; i < 4; i++) {
            int r = grp * 4 + i;
            float th = th_s[r];
            float nv = now_s[r][e];
            float val = sigf(sum[i] * th + nv * (1.f - th));
            vals[i] = val;
            g_dyn[(base + r) * 64 + e] = val;
            out_diffs[((size_t)(t - 1) * RLN + row0 + r) * 64 + e] = val - nv;
            if (t == T_ - 1) out_nowfinal[(size_t)(row0 + r) * 64 + e] = val;
        }
        __syncthreads();
#pragma unroll
        for (int i = 0; i < 4; i++) now_s[grp * 4 + i][e] = vals[i];
        __syncthreads();
    }
}

// =====================================================================
// 2. pass1: q/k GEMM, all 6 (b,g) batched.  grid 1500, block 256.
//    C[128 rows x 128 cols(q|k)] = X[128x64] @ [wq|wk]
// =====================================================================
__global__ void __launch_bounds__(256)
pass1_kernel(const float* __restrict__ stat,
             const float* __restrict__ wq_all,
             const float* __restrict__ wk_all,
             int s) {
    extern __shared__ float sm[];
    float* A_s = sm;                 // [128][68]
    float* W_s = sm + 128 * 68;      // [64][132]
    int tid = threadIdx.x;
    int bg = blockIdx.x / 250;
    int blk = blockIdx.x - bg * 250;

    const float* src;
    if (s == 0) src = (bg < 3) ? (const float*)g_dyn : stat;
    else        src = g_x6[bg];
    const float* wq = wq_all + (size_t)(bg * 2 + s) * 4096;
    const float* wk = wk_all + (size_t)(bg * 2 + s) * 4096;

    {
        const float4* wq4 = (const float4*)wq;
        const float4* wk4 = (const float4*)wk;
        for (int i = tid; i < 1024; i += 256) {
            int k = i >> 4, c4 = (i & 15) << 2;
            *(float4*)&W_s[k * 132 + c4] = wq4[i];
            *(float4*)&W_s[k * 132 + 64 + c4] = wk4[i];
        }
        const float4* x4 = (const float4*)(src + (size_t)blk * 128 * 64);
        for (int i = tid; i < 2048; i += 256) {
            int row = i >> 4, c4 = (i & 15) << 2;
            *(float4*)&A_s[row * 68 + c4] = x4[i];
        }
    }
    __syncthreads();

    int tx = tid & 15, ty = tid >> 4;
    float acc[8][8];
#pragma unroll
    for (int i = 0; i < 8; i++)
#pragma unroll
        for (int j = 0; j < 8; j++) acc[i][j] = 0.f;

#pragma unroll 4
    for (int k = 0; k < 64; k++) {
        float b[8];
        *(float4*)&b[0] = *(float4*)&W_s[k * 132 + tx * 8];
        *(float4*)&b[4] = *(float4*)&W_s[k * 132 + tx * 8 + 4];
        float a[8];
#pragma unroll
        for (int i = 0; i < 8; i++) a[i] = A_s[(ty + 16 * i) * 68 + k];
#pragma unroll
        for (int i = 0; i < 8; i++)
#pragma unroll
            for (int j = 0; j < 8; j++)
                acc[i][j] = fmaf(a[i], b[j], acc[i][j]);
    }

    float* qdst = g_q6[bg];
    float* kdst = g_k6[bg];
    size_t rowbase = (size_t)blk * 128;
#pragma unroll
    for (int i = 0; i < 8; i++) {
        size_t ro = (rowbase + ty + 16 * i) * 64;
        if (tx < 8) {
            *(float4*)&qdst[ro + tx * 8]     = make_float4(acc[i][0], acc[i][1], acc[i][2], acc[i][3]);
            *(float4*)&qdst[ro + tx * 8 + 4] = make_float4(acc[i][4], acc[i][5], acc[i][6], acc[i][7]);
        } else {
            *(float4*)&kdst[ro + (tx - 8) * 8]     = make_float4(acc[i][0], acc[i][1], acc[i][2], acc[i][3]);
            *(float4*)&kdst[ro + (tx - 8) * 8 + 4] = make_float4(acc[i][4], acc[i][5], acc[i][6], acc[i][7]);
        }
    }
}

// =====================================================================
// 3. pass2: gather + softmax attention + wd + sigmoid. grid 6000, block 256.
//    Phase A: 16-lane x 4-elem layout, 2 rows per warp at a time (4 total).
//    Phase B: wd GEMM, 2 cols/lane, 4 rows per warp.
// =====================================================================
__global__ void __launch_bounds__(256)
pass2_kernel(const int* __restrict__ n0,
             const int* __restrict__ n1,
             const int* __restrict__ n2,
             const float* __restrict__ wd_all,
             int s) {
    __shared__ float wdT_e[32 * 68];     // even cols: wd[d][2c] -> wdT_e[c][d]
    __shared__ float wdT_o[32 * 68];     // odd cols
    __shared__ float outbuf[8][4][64];
    int tid = threadIdx.x;
    int bg = blockIdx.x / 1000;
    int blk = blockIdx.x - bg * 1000;
    int gi3 = bg % 3;
    const int* neigh = (gi3 == 0) ? n0 : (gi3 == 1) ? n1 : n2;
    const float* wd = wd_all + (size_t)(bg * 2 + s) * 4096;

    for (int i = tid; i < 4096; i += 256) {
        int d = i >> 6, c = i & 63;
        float v = wd[i];
        if (c & 1) wdT_o[(c >> 1) * 68 + d] = v;
        else       wdT_e[(c >> 1) * 68 + d] = v;
    }
    __syncthreads();

    int w = tid >> 5, lane = tid & 31;
    int half = lane >> 4, l16 = lane & 15;
    const float* qb = g_q6[bg];
    const float* kb = g_k6[bg];

    // Phase A: each warp handles 4 rows as 2 pairs (one row per 16-lane half)
#pragma unroll
    for (int pr = 0; pr < 2; pr++) {
        int r = pr * 2 + half;
        int rowid = blk * 32 + w * 4 + r;
        int tl = rowid / N_;
        int n = rowid - tl * N_;
        const float* krow_base = kb + (size_t)tl * N_ * 64;
        float4 q = *(const float4*)&qb[(size_t)rowid * 64 + l16 * 4];
        float dots[K_];
        int nbs[K_];
#pragma unroll
        for (int j = 0; j < K_; j++) {
            int nb = __ldg(&neigh[n * K_ + j]);
            nbs[j] = nb;
            float4 kv = *(const float4*)&krow_base[(size_t)nb * 64 + l16 * 4];
            float d = q.x * kv.x + q.y * kv.y + q.z * kv.z + q.w * kv.w;
            d += __shfl_xor_sync(0xffffffffu, d, 8);
            d += __shfl_xor_sync(0xffffffffu, d, 4);
            d += __shfl_xor_sync(0xffffffffu, d, 2);
            d += __shfl_xor_sync(0xffffffffu, d, 1);
            dots[j] = d;
        }
        float m = dots[0];
#pragma unroll
        for (int j = 1; j < K_; j++) m = fmaxf(m, dots[j]);
        float ssum = 0.f;
#pragma unroll
        for (int j = 0; j < K_; j++) {
            dots[j] = __expf(dots[j] - m);
            ssum += dots[j];
        }
        float inv = 1.f / ssum;
        float4 o = q;
#pragma unroll
        for (int j = 0; j < K_; j++) {
            float a = dots[j] * inv;
            float4 kv = *(const float4*)&krow_base[(size_t)nbs[j] * 64 + l16 * 4];
            o.x = fmaf(a, kv.x, o.x);
            o.y = fmaf(a, kv.y, o.y);
            o.z = fmaf(a, kv.z, o.z);
            o.w = fmaf(a, kv.w, o.w);
        }
        *(float4*)&outbuf[w][r][l16 * 4] = o;
    }
    __syncwarp();

    // Phase B: out @ wd, cols (2*lane, 2*lane+1), 4 rows per warp
    float2 acc[4];
#pragma unroll
    for (int r = 0; r < 4; r++) acc[r] = make_float2(0.f, 0.f);
#pragma unroll
    for (int d = 0; d < 64; d += 4) {
        float4 wa = *(float4*)&wdT_e[lane * 68 + d];
        float4 wb = *(float4*)&wdT_o[lane * 68 + d];
#pragma unroll
        for (int r = 0; r < 4; r++) {
            float4 ov = *(float4*)&outbuf[w][r][d];
            acc[r].x += ov.x * wa.x + ov.y * wa.y + ov.z * wa.z + ov.w * wa.w;
            acc[r].y += ov.x * wb.x + ov.y * wb.y + ov.z * wb.z + ov.w * wb.w;
        }
    }
    float* xdst = g_x6[bg];
#pragma unroll
    for (int r = 0; r < 4; r++) {
        int rowid = blk * 32 + w * 4 + r;
        float2 v = make_float2(sigf(acc[r].x), sigf(acc[r].y));
        *(float2*)&xdst[(size_t)rowid * 64 + lane * 2] = v;
    }
}

// =====================================================================
// 4. mix: g_mixb[b] = sigmoid(sum_g x6[b*3+g] * wmix[b][g][e])
//    grid 16000, block 256
// =====================================================================
__global__ void mix_kernel(const float* __restrict__ wmix) {
    size_t gi = (size_t)blockIdx.x * 256 + threadIdx.x;
    int b = gi >= (size_t)ELEMS;
    size_t i = gi - (size_t)b * ELEMS;
    int e = (int)(i & 63);
    const float* wm = wmix + b * 192;
    float v = g_x6[b * 3 + 0][i] * wm[e]
            + g_x6[b * 3 + 1][i] * wm[64 + e]
            + g_x6[b * 3 + 2][i] * wm[128 + e];
    g_mixb[b][i] = sigf(v);
}

// =====================================================================
// 5. LSTM over L, warp per (t,n). grid 500 x 256
// =====================================================================
__global__ void lstm_kernel(const float* __restrict__ convw,
                            const float* __restrict__ convb) {
    __shared__ float cw[4 * 129];
    __shared__ float cb[4];
    int tid = threadIdx.x;
    for (int i = tid; i < 516; i += 256) cw[i] = convw[i];
    if (tid < 4) cb[tid] = convb[tid];
    __syncthreads();
    int gw = blockIdx.x * 8 + (tid >> 5);
    int lane = tid & 31;
    int t = gw / N_, n = gw % N_;
    int half = lane >> 4;           // 0: dyn, 1: sta
    int dl = (lane & 15) * 4;
    int dbase = half * 64 + dl;
    float wreg[4][4], wh[4], bb[4];
#pragma unroll
    for (int i = 0; i < 4; i++) {
#pragma unroll
        for (int q = 0; q < 4; q++) wreg[i][q] = cw[i * 129 + dbase + q];
        wh[i] = cw[i * 129 + 128];
        bb[i] = cb[i];
    }
    float h = 0.f, c = 0.f;
    for (int l = 0; l < L_; l++) {
        size_t off = (((size_t)t * L_ + l) * N_ + n) * 64 + dl;
        const float* src = half ? &g_mixb[1][off] : &g_mixb[0][off];
        float4 xin = *(const float4*)src;
        float s[4];
#pragma unroll
        for (int i = 0; i < 4; i++) {
            s[i] = xin.x * wreg[i][0] + xin.y * wreg[i][1] +
                   xin.z * wreg[i][2] + xin.w * wreg[i][3];
#pragma unroll
            for (int o = 16; o; o >>= 1)
                s[i] += __shfl_xor_sync(0xffffffffu, s[i], o);
        }
        float gi = sigf(s[0] + h * wh[0] + bb[0]);
        float gf = sigf(s[1] + h * wh[1] + bb[1]);
        float go = sigf(s[2] + h * wh[2] + bb[2]);
        float gg = tanhf(s[3] + h * wh[3] + bb[3]);
        c = gf * c + gi * gg;
        h = go * tanhf(c);
    }
    if (lane == 0) g_h[t * N_ + n] = h;
}

// =====================================================================
// 6. final projection: grid T_, block 512
// =====================================================================
__global__ void final_kernel(const float* __restrict__ finw,
                             const float* __restrict__ finb,
                             float* __restrict__ out) {
    __shared__ float hs[500];
    int t = blockIdx.x, tid = threadIdx.x;
    if (tid < 500) hs[tid] = g_h[t * N_ + tid];
    __syncthreads();
    if (tid < 500) {
        float acc = finb[tid];
        const float4* wr = (const float4*)(finw + (size_t)tid * 500);
#pragma unroll 5
        for (int m4 = 0; m4 < 125; m4++) {
            float4 wv = wr[m4];
            acc = fmaf(hs[m4 * 4 + 0], wv.x, acc);
            acc = fmaf(hs[m4 * 4 + 1], wv.y, acc);
            acc = fmaf(hs[m4 * 4 + 2], wv.z, acc);
            acc = fmaf(hs[m4 * 4 + 3], wv.w, acc);
        }
        out[t * N_ + tid] = sigf(acc);
    }
}

// ---------------- launcher ----------------
extern "C" void kernel_launch(void* const* d_in, const int* in_sizes, int n_in,
                              void* d_out, int out_size) {
    const float* stat = (const float*)d_in[0];   // all_data_static (T,L,N,D)
    const float* thre = (const float*)d_in[1];   // thre_nc (T,L,N,1)
    const float* dynn = (const float*)d_in[2];   // all_data_dynamic_now (L,N,D)
    const int* npoi = (const int*)d_in[3];
    const int* nroad = (const int*)d_in[4];
    const int* nrec = (const int*)d_in[5];
    const float* w1 = (const float*)d_in[6];     // (128,64)
    const float* wq = (const float*)d_in[7];     // (2,3,S,D,D)
    const float* wk = (const float*)d_in[8];
    const float* wdm = (const float*)d_in[9];
    const float* wmix = (const float*)d_in[10];  // (2,3,D)
    const float* convw = (const float*)d_in[11]; // (4,129)
    const float* convb = (const float*)d_in[12]; // (4,)
    const float* finw = (const float*)d_in[13];  // (N,N)
    const float* finb = (const float*)d_in[14];  // (N,)

    float* out = (float*)d_out;
    float* out_scores = out;                          // (T,N)       4000
    float* out_nowfinal = out + T_ * N_;              // (L,N,D)     256000
    float* out_diffs = out + T_ * N_ + L_ * N_ * D_;  // (T-1,L,N,D) 1792000

    static const int PASS1_SMEM = (128 * 68 + 64 * 132) * 4;   // 68608 B
    cudaFuncSetAttribute(pass1_kernel,
                         cudaFuncAttributeMaxDynamicSharedMemorySize, PASS1_SMEM);

    evo_kernel<<<250, 256>>>(stat, thre, dynn, w1, out_nowfinal, out_diffs);

    for (int s = 0; s < S_; s++) {
        pass1_kernel<<<1500, 256, PASS1_SMEM>>>(stat, wq, wk, s);
        pass2_kernel<<<6000, 256>>>(npoi, nroad, nrec, wdm, s);
    }

    mix_kernel<<<16000, 256>>>(wmix);
    lstm_kernel<<<500, 256>>>(convw, convb);
    final_kernel<<<T_, 512>>>(finw, finb, out_scores);
}